// round 1
// baseline (speedup 1.0000x reference)
#include <cuda_runtime.h>
#include <math.h>

#define BSZ  4
#define NSEQ 2048
#define EMB  1024
#define HNUM 16
#define DH   64
#define SCALE 0.125f  // 1/sqrt(64)

// Scratch (device globals — no allocation allowed)
__device__ float g_Q[BSZ * NSEQ * EMB];
__device__ float g_K[BSZ * NSEQ * EMB];
__device__ float g_V[BSZ * NSEQ * EMB];
__device__ float g_C[BSZ * NSEQ * EMB];

// ---------------------------------------------------------------------------
// GEMM: C[M,Ncol] = A[M,K] @ W[Ncol,K]^T (+ bias). Both A and W are K-contiguous.
// 64x64 tile, BK=64, 256 threads, 4x4 per thread, transposed smem tiles (pad 68).
// ---------------------------------------------------------------------------
template <bool BIAS>
__global__ __launch_bounds__(256)
void gemm_xwT(const float* __restrict__ A, const float* __restrict__ W,
              const float* __restrict__ bias, float* __restrict__ C,
              int M, int Ncol, int K)
{
    __shared__ float As[64 * 68];  // As[k][m]
    __shared__ float Bs[64 * 68];  // Bs[k][n]

    const int tid = threadIdx.x;
    const int tx = tid & 15;
    const int ty = tid >> 4;
    const int m0 = blockIdx.y * 64;
    const int n0 = blockIdx.x * 64;

    float acc[4][4];
#pragma unroll
    for (int i = 0; i < 4; i++)
#pragma unroll
        for (int j = 0; j < 4; j++) acc[i][j] = 0.f;

    for (int k0 = 0; k0 < K; k0 += 64) {
#pragma unroll
        for (int t = 0; t < 4; t++) {
            int v = tid + t * 256;          // [0,1024)
            int row = v >> 4;               // [0,64)
            int c4  = v & 15;               // [0,16)
            float4 fa = *(const float4*)&A[(m0 + row) * K + k0 + c4 * 4];
            As[(c4 * 4 + 0) * 68 + row] = fa.x;
            As[(c4 * 4 + 1) * 68 + row] = fa.y;
            As[(c4 * 4 + 2) * 68 + row] = fa.z;
            As[(c4 * 4 + 3) * 68 + row] = fa.w;
            float4 fb = *(const float4*)&W[(n0 + row) * K + k0 + c4 * 4];
            Bs[(c4 * 4 + 0) * 68 + row] = fb.x;
            Bs[(c4 * 4 + 1) * 68 + row] = fb.y;
            Bs[(c4 * 4 + 2) * 68 + row] = fb.z;
            Bs[(c4 * 4 + 3) * 68 + row] = fb.w;
        }
        __syncthreads();

#pragma unroll 16
        for (int kk = 0; kk < 64; kk++) {
            float4 a = *(const float4*)(As + kk * 68 + (ty << 2));
            float4 b = *(const float4*)(Bs + kk * 68 + (tx << 2));
            float ar[4] = {a.x, a.y, a.z, a.w};
            float br[4] = {b.x, b.y, b.z, b.w};
#pragma unroll
            for (int i = 0; i < 4; i++)
#pragma unroll
                for (int j = 0; j < 4; j++) acc[i][j] += ar[i] * br[j];
        }
        __syncthreads();
    }

#pragma unroll
    for (int i = 0; i < 4; i++) {
        int r = m0 + ty * 4 + i;
        int c = n0 + tx * 4;
        float4 outv;
        outv.x = acc[i][0]; outv.y = acc[i][1]; outv.z = acc[i][2]; outv.w = acc[i][3];
        if (BIAS) {
            outv.x += bias[c + 0]; outv.y += bias[c + 1];
            outv.z += bias[c + 2]; outv.w += bias[c + 3];
        }
        *(float4*)&C[r * Ncol + c] = outv;
    }
}

// ---------------------------------------------------------------------------
// Flash attention (causal). Block = 256 threads handles (b, h, 64 query rows).
// smem: sQ[d][r] (64x68), sKV (K as [d][c], then V as [kk][c], 64x68),
//       sP[r][c] scores/probs (64x68). Dynamic smem = 52224 bytes.
// ---------------------------------------------------------------------------
__global__ __launch_bounds__(256)
void attn_kernel(const float* __restrict__ Q, const float* __restrict__ K,
                 const float* __restrict__ V, float* __restrict__ O)
{
    extern __shared__ float sm[];
    float* sQ  = sm;                 // [64][68], d-major
    float* sKV = sm + 64 * 68;       // K: [d][c] ; V: [kk][c]
    float* sP  = sm + 2 * 64 * 68;   // [r][c]

    const int tid = threadIdx.x;
    const int qt = blockIdx.x;       // query tile
    const int bh = blockIdx.y;
    const int b = bh >> 4, h = bh & 15;
    const int base = (b * NSEQ) * EMB + h * DH;
    const int qbase = qt * 64;

    // Load Q tile (transposed: sQ[d][r])
#pragma unroll
    for (int t = 0; t < 4; t++) {
        int v = tid + t * 256;
        int row = v >> 4, c4 = v & 15;
        float4 f = *(const float4*)&Q[base + (qbase + row) * EMB + c4 * 4];
        sQ[(c4 * 4 + 0) * 68 + row] = f.x;
        sQ[(c4 * 4 + 1) * 68 + row] = f.y;
        sQ[(c4 * 4 + 2) * 68 + row] = f.z;
        sQ[(c4 * 4 + 3) * 68 + row] = f.w;
    }

    const int tx = tid & 15, ty = tid >> 4;     // S-compute map (4x4 tiles)
    const int rrow = tid >> 2, cg = tid & 3;    // row map: 4 threads/row, 16 cols each

    float o[16];
#pragma unroll
    for (int u = 0; u < 16; u++) o[u] = 0.f;
    float m_old = -INFINITY;
    float l = 0.f;

    for (int j = 0; j <= qt; j++) {
        __syncthreads();  // prev O-phase done with sKV/sP (covers Q load on iter 0)

        // Load K tile transposed: sKV[d][c]
#pragma unroll
        for (int t = 0; t < 4; t++) {
            int v = tid + t * 256;
            int row = v >> 4, c4 = v & 15;
            float4 f = *(const float4*)&K[base + (j * 64 + row) * EMB + c4 * 4];
            sKV[(c4 * 4 + 0) * 68 + row] = f.x;
            sKV[(c4 * 4 + 1) * 68 + row] = f.y;
            sKV[(c4 * 4 + 2) * 68 + row] = f.z;
            sKV[(c4 * 4 + 3) * 68 + row] = f.w;
        }
        __syncthreads();

        // S = Q K^T  (64x64x64)
        float acc[4][4];
#pragma unroll
        for (int i = 0; i < 4; i++)
#pragma unroll
            for (int jj = 0; jj < 4; jj++) acc[i][jj] = 0.f;
#pragma unroll 16
        for (int kk = 0; kk < 64; kk++) {
            float4 a = *(const float4*)(sQ + kk * 68 + (ty << 2));
            float4 bb = *(const float4*)(sKV + kk * 68 + (tx << 2));
            float ar[4] = {a.x, a.y, a.z, a.w};
            float br[4] = {bb.x, bb.y, bb.z, bb.w};
#pragma unroll
            for (int i = 0; i < 4; i++)
#pragma unroll
                for (int jj = 0; jj < 4; jj++) acc[i][jj] += ar[i] * br[jj];
        }
        // Write scaled + masked scores to sP
#pragma unroll
        for (int i = 0; i < 4; i++) {
            int r = ty * 4 + i;
            int qg = qbase + r;
            int c0 = tx * 4;
            int kg = j * 64 + c0;
            float4 sv;
            sv.x = (kg + 0 <= qg) ? acc[i][0] * SCALE : -1e30f;
            sv.y = (kg + 1 <= qg) ? acc[i][1] * SCALE : -1e30f;
            sv.z = (kg + 2 <= qg) ? acc[i][2] * SCALE : -1e30f;
            sv.w = (kg + 3 <= qg) ? acc[i][3] * SCALE : -1e30f;
            *(float4*)(sP + r * 68 + c0) = sv;
        }
        __syncthreads();

        // Load V tile (row-major) into sKV — K reads are done
#pragma unroll
        for (int t = 0; t < 4; t++) {
            int v = tid + t * 256;
            int row = v >> 4, c4 = v & 15;
            float4 f = *(const float4*)&V[base + (j * 64 + row) * EMB + c4 * 4];
            *(float4*)(sKV + row * 68 + c4 * 4) = f;
        }

        // Online softmax (row map)
        float p[16];
        float mt = -INFINITY;
        const float* srow = sP + rrow * 68 + cg * 16;
#pragma unroll
        for (int u = 0; u < 16; u++) { p[u] = srow[u]; mt = fmaxf(mt, p[u]); }
        mt = fmaxf(mt, __shfl_xor_sync(0xffffffffu, mt, 1));
        mt = fmaxf(mt, __shfl_xor_sync(0xffffffffu, mt, 2));
        float m_new = fmaxf(m_old, mt);
        float alpha = __expf(m_old - m_new);  // 0 when m_old == -inf
        float sum = 0.f;
#pragma unroll
        for (int u = 0; u < 16; u++) { p[u] = __expf(p[u] - m_new); sum += p[u]; }
        sum += __shfl_xor_sync(0xffffffffu, sum, 1);
        sum += __shfl_xor_sync(0xffffffffu, sum, 2);
        l = l * alpha + sum;
#pragma unroll
        for (int u = 0; u < 16; u++) o[u] *= alpha;
        m_old = m_new;
        float* prow = sP + rrow * 68 + cg * 16;
#pragma unroll
        for (int w = 0; w < 4; w++) {
            float4 pv;
            pv.x = p[4 * w + 0]; pv.y = p[4 * w + 1];
            pv.z = p[4 * w + 2]; pv.w = p[4 * w + 3];
            *(float4*)(prow + 4 * w) = pv;
        }
        __syncthreads();

        // O += P @ V
#pragma unroll 8
        for (int kk = 0; kk < 64; kk++) {
            float pv = sP[rrow * 68 + kk];
            const float* vr = sKV + kk * 68 + cg * 16;
#pragma unroll
            for (int w = 0; w < 4; w++) {
                float4 vv = *(const float4*)(vr + 4 * w);
                o[4 * w + 0] += pv * vv.x;
                o[4 * w + 1] += pv * vv.y;
                o[4 * w + 2] += pv * vv.z;
                o[4 * w + 3] += pv * vv.w;
            }
        }
    }

    // Epilogue: normalize and store ctx as [B,N,E]
    float inv = 1.f / l;
#pragma unroll
    for (int w = 0; w < 4; w++) {
        float4 outv;
        outv.x = o[4 * w + 0] * inv; outv.y = o[4 * w + 1] * inv;
        outv.z = o[4 * w + 2] * inv; outv.w = o[4 * w + 3] * inv;
        *(float4*)&O[base + (qbase + rrow) * EMB + cg * 16 + 4 * w] = outv;
    }
}

// ---------------------------------------------------------------------------
extern "C" void kernel_launch(void* const* d_in, const int* in_sizes, int n_in,
                              void* d_out, int out_size)
{
    const float* xq = (const float*)d_in[0];
    const float* xk = (const float*)d_in[1];
    const float* xv = (const float*)d_in[2];
    // d_in[3] = attn_mask (causal triu) — implemented analytically, ignored
    const float* Wq = (const float*)d_in[4];
    const float* Wk = (const float*)d_in[5];
    const float* Wv = (const float*)d_in[6];
    const float* Wo = (const float*)d_in[7];
    const float* bo = (const float*)d_in[8];
    float* out = (float*)d_out;

    float *q, *k, *v, *c;
    cudaGetSymbolAddress((void**)&q, g_Q);
    cudaGetSymbolAddress((void**)&k, g_K);
    cudaGetSymbolAddress((void**)&v, g_V);
    cudaGetSymbolAddress((void**)&c, g_C);

    const int M = BSZ * NSEQ;
    const int attn_smem = 3 * 64 * 68 * (int)sizeof(float);  // 52224
    cudaFuncSetAttribute(attn_kernel, cudaFuncAttributeMaxDynamicSharedMemorySize,
                         attn_smem);

    dim3 gg(EMB / 64, M / 64);  // (16, 128)
    gemm_xwT<false><<<gg, 256>>>(xq, Wq, nullptr, q, M, EMB, EMB);
    gemm_xwT<false><<<gg, 256>>>(xk, Wk, nullptr, k, M, EMB, EMB);
    gemm_xwT<false><<<gg, 256>>>(xv, Wv, nullptr, v, M, EMB, EMB);

    attn_kernel<<<dim3(NSEQ / 64, BSZ * HNUM), 256, attn_smem>>>(q, k, v, c);

    gemm_xwT<true><<<gg, 256>>>(c, Wo, bo, out, M, EMB, EMB);
}

// round 5
// speedup vs baseline: 1.5466x; 1.5466x over previous
#include <cuda_runtime.h>
#include <cstdint>
#include <math.h>

#define BSZ  4
#define NSEQ 2048
#define EMB  1024
#define HNUM 16
#define DH   64
#define SCALE 0.125f  // 1/sqrt(64)

// Scratch (device globals — no allocation allowed)
__device__ float g_Q[BSZ * NSEQ * EMB];
__device__ float g_K[BSZ * NSEQ * EMB];
__device__ float g_V[BSZ * NSEQ * EMB];
__device__ float g_C[BSZ * NSEQ * EMB];

__device__ __forceinline__ float to_tf32(float x) {
    float r;
    asm("cvt.rna.tf32.f32 %0, %1;" : "=f"(r) : "f"(x));
    return r;
}

__device__ __forceinline__ void mma_tf32(float* d, const uint32_t* a, const uint32_t* b) {
    asm volatile(
        "mma.sync.aligned.m16n8k8.row.col.f32.tf32.tf32.f32 "
        "{%0,%1,%2,%3}, {%4,%5,%6,%7}, {%8,%9}, {%0,%1,%2,%3};"
        : "+f"(d[0]), "+f"(d[1]), "+f"(d[2]), "+f"(d[3])
        : "r"(a[0]), "r"(a[1]), "r"(a[2]), "r"(a[3]), "r"(b[0]), "r"(b[1]));
}

// ===========================================================================
// HMMA tf32 GEMM: C[M,Ncol] = A[M,K] @ W[Ncol,K]^T (+ bias)
// CTA 128x128, BK=32, 256 threads = 8 warps (4M x 2N), warp tile 32x64.
// smem tiles [row][k] padded to stride 36 floats (conflict-free frag loads).
// ===========================================================================
#define BK 32
#define LDS_STRIDE 36

template <bool BIAS>
__global__ __launch_bounds__(256)
void gemm_tc(const float* __restrict__ A, const float* __restrict__ W,
             const float* __restrict__ bias, float* __restrict__ C,
             int M, int Ncol, int K)
{
    __shared__ uint32_t sA[128 * LDS_STRIDE];
    __shared__ uint32_t sB[128 * LDS_STRIDE];

    const int tid = threadIdx.x;
    const int wid = tid >> 5;
    const int lane = tid & 31;
    const int g = lane >> 2;        // group id (0..7)
    const int t = lane & 3;         // thread-in-group (0..3)
    const int wm = wid >> 1;        // 0..3 (M dir)
    const int wn = wid & 1;         // 0..1 (N dir)
    const int m0 = blockIdx.y * 128;
    const int n0 = blockIdx.x * 128;

    float d[2][8][4];
#pragma unroll
    for (int i = 0; i < 2; i++)
#pragma unroll
        for (int j = 0; j < 8; j++)
#pragma unroll
            for (int q = 0; q < 4; q++) d[i][j][q] = 0.f;

    const int nchunks = K / BK;
    for (int c = 0; c < nchunks; ++c) {
        const int k0 = c * BK;
        // ---- Stage A, B chunks into smem (tf32-converted) ----
#pragma unroll
        for (int i = 0; i < 4; i++) {
            int idx = i * 256 + tid;        // 0..1023
            int row = idx >> 3;             // 0..127
            int c4  = idx & 7;              // 0..7
            float4 fa = *(const float4*)&A[(size_t)(m0 + row) * K + k0 + c4 * 4];
            float4 fb = *(const float4*)&W[(size_t)(n0 + row) * K + k0 + c4 * 4];
            uint32_t* pa = sA + row * LDS_STRIDE + c4 * 4;
            uint32_t* pb = sB + row * LDS_STRIDE + c4 * 4;
            pa[0] = __float_as_uint(to_tf32(fa.x));
            pa[1] = __float_as_uint(to_tf32(fa.y));
            pa[2] = __float_as_uint(to_tf32(fa.z));
            pa[3] = __float_as_uint(to_tf32(fa.w));
            pb[0] = __float_as_uint(to_tf32(fb.x));
            pb[1] = __float_as_uint(to_tf32(fb.y));
            pb[2] = __float_as_uint(to_tf32(fb.z));
            pb[3] = __float_as_uint(to_tf32(fb.w));
        }
        __syncthreads();

        // ---- Compute: 4 k-steps of m16n8k8 ----
#pragma unroll
        for (int ks = 0; ks < 4; ks++) {
            const int kb = ks * 8;
            uint32_t af[2][4];
#pragma unroll
            for (int mf = 0; mf < 2; mf++) {
                const uint32_t* base = sA + (wm * 32 + mf * 16 + g) * LDS_STRIDE + kb + t;
                af[mf][0] = base[0];
                af[mf][1] = base[8 * LDS_STRIDE];
                af[mf][2] = base[4];
                af[mf][3] = base[8 * LDS_STRIDE + 4];
            }
            uint32_t bf[8][2];
#pragma unroll
            for (int nf = 0; nf < 8; nf++) {
                const uint32_t* base = sB + (wn * 64 + nf * 8 + g) * LDS_STRIDE + kb + t;
                bf[nf][0] = base[0];
                bf[nf][1] = base[4];
            }
#pragma unroll
            for (int mf = 0; mf < 2; mf++)
#pragma unroll
                for (int nf = 0; nf < 8; nf++)
                    mma_tf32(d[mf][nf], af[mf], bf[nf]);
        }
        __syncthreads();
    }

    // ---- Epilogue ----
#pragma unroll
    for (int mf = 0; mf < 2; mf++) {
        const int r0 = m0 + wm * 32 + mf * 16 + g;
#pragma unroll
        for (int nf = 0; nf < 8; nf++) {
            const int col = n0 + wn * 64 + nf * 8 + 2 * t;
            float2 v0, v1;
            v0.x = d[mf][nf][0]; v0.y = d[mf][nf][1];
            v1.x = d[mf][nf][2]; v1.y = d[mf][nf][3];
            if (BIAS) {
                const float2 bv = *(const float2*)&bias[col];
                v0.x += bv.x; v0.y += bv.y;
                v1.x += bv.x; v1.y += bv.y;
            }
            *(float2*)&C[(size_t)r0 * Ncol + col] = v0;
            *(float2*)&C[(size_t)(r0 + 8) * Ncol + col] = v1;
        }
    }
}

// ---------------------------------------------------------------------------
// Flash attention (causal) — unchanged fp32 version (known correct).
// ---------------------------------------------------------------------------
__global__ __launch_bounds__(256)
void attn_kernel(const float* __restrict__ Q, const float* __restrict__ K,
                 const float* __restrict__ V, float* __restrict__ O)
{
    extern __shared__ float sm[];
    float* sQ  = sm;                 // [64][68], d-major
    float* sKV = sm + 64 * 68;       // K: [d][c] ; V: [kk][c]
    float* sP  = sm + 2 * 64 * 68;   // [r][c]

    const int tid = threadIdx.x;
    const int qt = blockIdx.x;       // query tile
    const int bh = blockIdx.y;
    const int b = bh >> 4, h = bh & 15;
    const int base = (b * NSEQ) * EMB + h * DH;
    const int qbase = qt * 64;

#pragma unroll
    for (int t = 0; t < 4; t++) {
        int v = tid + t * 256;
        int row = v >> 4, c4 = v & 15;
        float4 f = *(const float4*)&Q[base + (qbase + row) * EMB + c4 * 4];
        sQ[(c4 * 4 + 0) * 68 + row] = f.x;
        sQ[(c4 * 4 + 1) * 68 + row] = f.y;
        sQ[(c4 * 4 + 2) * 68 + row] = f.z;
        sQ[(c4 * 4 + 3) * 68 + row] = f.w;
    }

    const int tx = tid & 15, ty = tid >> 4;
    const int rrow = tid >> 2, cg = tid & 3;

    float o[16];
#pragma unroll
    for (int u = 0; u < 16; u++) o[u] = 0.f;
    float m_old = -INFINITY;
    float l = 0.f;

    for (int j = 0; j <= qt; j++) {
        __syncthreads();

#pragma unroll
        for (int t = 0; t < 4; t++) {
            int v = tid + t * 256;
            int row = v >> 4, c4 = v & 15;
            float4 f = *(const float4*)&K[base + (j * 64 + row) * EMB + c4 * 4];
            sKV[(c4 * 4 + 0) * 68 + row] = f.x;
            sKV[(c4 * 4 + 1) * 68 + row] = f.y;
            sKV[(c4 * 4 + 2) * 68 + row] = f.z;
            sKV[(c4 * 4 + 3) * 68 + row] = f.w;
        }
        __syncthreads();

        float acc[4][4];
#pragma unroll
        for (int i = 0; i < 4; i++)
#pragma unroll
            for (int jj = 0; jj < 4; jj++) acc[i][jj] = 0.f;
#pragma unroll 16
        for (int kk = 0; kk < 64; kk++) {
            float4 a = *(const float4*)(sQ + kk * 68 + (ty << 2));
            float4 bb = *(const float4*)(sKV + kk * 68 + (tx << 2));
            float ar[4] = {a.x, a.y, a.z, a.w};
            float br[4] = {bb.x, bb.y, bb.z, bb.w};
#pragma unroll
            for (int i = 0; i < 4; i++)
#pragma unroll
                for (int jj = 0; jj < 4; jj++) acc[i][jj] += ar[i] * br[jj];
        }
#pragma unroll
        for (int i = 0; i < 4; i++) {
            int r = ty * 4 + i;
            int qg = qbase + r;
            int c0 = tx * 4;
            int kg = j * 64 + c0;
            float4 sv;
            sv.x = (kg + 0 <= qg) ? acc[i][0] * SCALE : -1e30f;
            sv.y = (kg + 1 <= qg) ? acc[i][1] * SCALE : -1e30f;
            sv.z = (kg + 2 <= qg) ? acc[i][2] * SCALE : -1e30f;
            sv.w = (kg + 3 <= qg) ? acc[i][3] * SCALE : -1e30f;
            *(float4*)(sP + r * 68 + c0) = sv;
        }
        __syncthreads();

#pragma unroll
        for (int t = 0; t < 4; t++) {
            int v = tid + t * 256;
            int row = v >> 4, c4 = v & 15;
            float4 f = *(const float4*)&V[base + (j * 64 + row) * EMB + c4 * 4];
            *(float4*)(sKV + row * 68 + c4 * 4) = f;
        }

        float p[16];
        float mt = -INFINITY;
        const float* srow = sP + rrow * 68 + cg * 16;
#pragma unroll
        for (int u = 0; u < 16; u++) { p[u] = srow[u]; mt = fmaxf(mt, p[u]); }
        mt = fmaxf(mt, __shfl_xor_sync(0xffffffffu, mt, 1));
        mt = fmaxf(mt, __shfl_xor_sync(0xffffffffu, mt, 2));
        float m_new = fmaxf(m_old, mt);
        float alpha = __expf(m_old - m_new);
        float sum = 0.f;
#pragma unroll
        for (int u = 0; u < 16; u++) { p[u] = __expf(p[u] - m_new); sum += p[u]; }
        sum += __shfl_xor_sync(0xffffffffu, sum, 1);
        sum += __shfl_xor_sync(0xffffffffu, sum, 2);
        l = l * alpha + sum;
#pragma unroll
        for (int u = 0; u < 16; u++) o[u] *= alpha;
        m_old = m_new;
        float* prow = sP + rrow * 68 + cg * 16;
#pragma unroll
        for (int w = 0; w < 4; w++) {
            float4 pv;
            pv.x = p[4 * w + 0]; pv.y = p[4 * w + 1];
            pv.z = p[4 * w + 2]; pv.w = p[4 * w + 3];
            *(float4*)(prow + 4 * w) = pv;
        }
        __syncthreads();

#pragma unroll 8
        for (int kk = 0; kk < 64; kk++) {
            float pv = sP[rrow * 68 + kk];
            const float* vr = sKV + kk * 68 + cg * 16;
#pragma unroll
            for (int w = 0; w < 4; w++) {
                float4 vv = *(const float4*)(vr + 4 * w);
                o[4 * w + 0] += pv * vv.x;
                o[4 * w + 1] += pv * vv.y;
                o[4 * w + 2] += pv * vv.z;
                o[4 * w + 3] += pv * vv.w;
            }
        }
    }

    float inv = 1.f / l;
#pragma unroll
    for (int w = 0; w < 4; w++) {
        float4 outv;
        outv.x = o[4 * w + 0] * inv; outv.y = o[4 * w + 1] * inv;
        outv.z = o[4 * w + 2] * inv; outv.w = o[4 * w + 3] * inv;
        *(float4*)&O[base + (qbase + rrow) * EMB + cg * 16 + 4 * w] = outv;
    }
}

// ---------------------------------------------------------------------------
extern "C" void kernel_launch(void* const* d_in, const int* in_sizes, int n_in,
                              void* d_out, int out_size)
{
    const float* xq = (const float*)d_in[0];
    const float* xk = (const float*)d_in[1];
    const float* xv = (const float*)d_in[2];
    // d_in[3] = attn_mask (causal triu) — implemented analytically, ignored
    const float* Wq = (const float*)d_in[4];
    const float* Wk = (const float*)d_in[5];
    const float* Wv = (const float*)d_in[6];
    const float* Wo = (const float*)d_in[7];
    const float* bo = (const float*)d_in[8];
    float* out = (float*)d_out;

    float *q, *k, *v, *c;
    cudaGetSymbolAddress((void**)&q, g_Q);
    cudaGetSymbolAddress((void**)&k, g_K);
    cudaGetSymbolAddress((void**)&v, g_V);
    cudaGetSymbolAddress((void**)&c, g_C);

    const int M = BSZ * NSEQ;
    const int attn_smem = 3 * 64 * 68 * (int)sizeof(float);  // 52224
    cudaFuncSetAttribute(attn_kernel, cudaFuncAttributeMaxDynamicSharedMemorySize,
                         attn_smem);

    dim3 gg(EMB / 128, M / 128);  // (8, 64)
    gemm_tc<false><<<gg, 256>>>(xq, Wq, nullptr, q, M, EMB, EMB);
    gemm_tc<false><<<gg, 256>>>(xk, Wk, nullptr, k, M, EMB, EMB);
    gemm_tc<false><<<gg, 256>>>(xv, Wv, nullptr, v, M, EMB, EMB);

    attn_kernel<<<dim3(NSEQ / 64, BSZ * HNUM), 256, attn_smem>>>(q, k, v, c);

    gemm_tc<true><<<gg, 256>>>(c, Wo, bo, out, M, EMB, EMB);
}

// round 6
// speedup vs baseline: 1.8244x; 1.1796x over previous
#include <cuda_runtime.h>
#include <cstdint>
#include <math.h>

#define BSZ  4
#define NSEQ 2048
#define EMB  1024
#define HNUM 16
#define DH   64
#define SCALE 0.125f  // 1/sqrt(64)

// Scratch (device globals — no allocation allowed)
__device__ float g_Q[BSZ * NSEQ * EMB];
__device__ float g_K[BSZ * NSEQ * EMB];
__device__ float g_V[BSZ * NSEQ * EMB];
__device__ float g_C[BSZ * NSEQ * EMB];

__device__ __forceinline__ float to_tf32(float x) {
    float r;
    asm("cvt.rna.tf32.f32 %0, %1;" : "=f"(r) : "f"(x));
    return r;
}

__device__ __forceinline__ void mma_tf32(float* d, const uint32_t* a, const uint32_t* b) {
    asm volatile(
        "mma.sync.aligned.m16n8k8.row.col.f32.tf32.tf32.f32 "
        "{%0,%1,%2,%3}, {%4,%5,%6,%7}, {%8,%9}, {%0,%1,%2,%3};"
        : "+f"(d[0]), "+f"(d[1]), "+f"(d[2]), "+f"(d[3])
        : "r"(a[0]), "r"(a[1]), "r"(a[2]), "r"(a[3]), "r"(b[0]), "r"(b[1]));
}

// ===========================================================================
// 3xTF32 split GEMM: C[M,Ncol] = A[M,K] @ W[Ncol,K]^T (+ bias), ~fp32 accuracy.
// CTA 128x128, BK=32, 256 threads = 8 warps (4M x 2N), warp tile 32x64.
// smem holds raw fp32; hi/lo tf32 split done at fragment load.
// ===========================================================================
#define BK 32
#define LDSS 36

template <bool BIAS>
__global__ __launch_bounds__(256)
void gemm_tc(const float* __restrict__ A, const float* __restrict__ W,
             const float* __restrict__ bias, float* __restrict__ C,
             int M, int Ncol, int K)
{
    __shared__ float sA[128 * LDSS];
    __shared__ float sB[128 * LDSS];

    const int tid = threadIdx.x;
    const int wid = tid >> 5;
    const int lane = tid & 31;
    const int g = lane >> 2;
    const int t = lane & 3;
    const int wm = wid >> 1;        // 0..3 (M dir)
    const int wn = wid & 1;         // 0..1 (N dir)
    const int m0 = blockIdx.y * 128;
    const int n0 = blockIdx.x * 128;

    float d[2][8][4];
#pragma unroll
    for (int i = 0; i < 2; i++)
#pragma unroll
        for (int j = 0; j < 8; j++)
#pragma unroll
            for (int q = 0; q < 4; q++) d[i][j][q] = 0.f;

    const int nchunks = K / BK;
    for (int c = 0; c < nchunks; ++c) {
        const int k0 = c * BK;
#pragma unroll
        for (int i = 0; i < 4; i++) {
            int idx = i * 256 + tid;
            int row = idx >> 3;
            int c4  = idx & 7;
            float4 fa = *(const float4*)&A[(size_t)(m0 + row) * K + k0 + c4 * 4];
            float4 fb = *(const float4*)&W[(size_t)(n0 + row) * K + k0 + c4 * 4];
            *(float4*)(sA + row * LDSS + c4 * 4) = fa;
            *(float4*)(sB + row * LDSS + c4 * 4) = fb;
        }
        __syncthreads();

#pragma unroll
        for (int ks = 0; ks < 4; ks++) {
            const int kb = ks * 8;
            uint32_t ah[2][4], al[2][4];
#pragma unroll
            for (int mf = 0; mf < 2; mf++) {
                const float* base = sA + (wm * 32 + mf * 16 + g) * LDSS + kb + t;
                float x0 = base[0], x1 = base[8 * LDSS], x2 = base[4], x3 = base[8 * LDSS + 4];
                float h0 = to_tf32(x0), h1 = to_tf32(x1), h2 = to_tf32(x2), h3 = to_tf32(x3);
                ah[mf][0] = __float_as_uint(h0); al[mf][0] = __float_as_uint(to_tf32(x0 - h0));
                ah[mf][1] = __float_as_uint(h1); al[mf][1] = __float_as_uint(to_tf32(x1 - h1));
                ah[mf][2] = __float_as_uint(h2); al[mf][2] = __float_as_uint(to_tf32(x2 - h2));
                ah[mf][3] = __float_as_uint(h3); al[mf][3] = __float_as_uint(to_tf32(x3 - h3));
            }
#pragma unroll
            for (int half = 0; half < 2; half++) {
                uint32_t bh_[4][2], bl_[4][2];
#pragma unroll
                for (int nh = 0; nh < 4; nh++) {
                    const int nf = half * 4 + nh;
                    const float* base = sB + (wn * 64 + nf * 8 + g) * LDSS + kb + t;
                    float x0 = base[0], x1 = base[4];
                    float h0 = to_tf32(x0), h1 = to_tf32(x1);
                    bh_[nh][0] = __float_as_uint(h0); bl_[nh][0] = __float_as_uint(to_tf32(x0 - h0));
                    bh_[nh][1] = __float_as_uint(h1); bl_[nh][1] = __float_as_uint(to_tf32(x1 - h1));
                }
#pragma unroll
                for (int mf = 0; mf < 2; mf++)
#pragma unroll
                    for (int nh = 0; nh < 4; nh++) {
                        const int nf = half * 4 + nh;
                        mma_tf32(d[mf][nf], ah[mf], bh_[nh]);
                        mma_tf32(d[mf][nf], ah[mf], bl_[nh]);
                        mma_tf32(d[mf][nf], al[mf], bh_[nh]);
                    }
            }
        }
        __syncthreads();
    }

#pragma unroll
    for (int mf = 0; mf < 2; mf++) {
        const int r0 = m0 + wm * 32 + mf * 16 + g;
#pragma unroll
        for (int nf = 0; nf < 8; nf++) {
            const int col = n0 + wn * 64 + nf * 8 + 2 * t;
            float2 v0, v1;
            v0.x = d[mf][nf][0]; v0.y = d[mf][nf][1];
            v1.x = d[mf][nf][2]; v1.y = d[mf][nf][3];
            if (BIAS) {
                const float2 bv = *(const float2*)&bias[col];
                v0.x += bv.x; v0.y += bv.y;
                v1.x += bv.x; v1.y += bv.y;
            }
            *(float2*)&C[(size_t)r0 * Ncol + col] = v0;
            *(float2*)&C[(size_t)(r0 + 8) * Ncol + col] = v1;
        }
    }
}

// ===========================================================================
// Tensor-core flash attention (causal), tf32 HMMA.
// Block = 128 threads (4 warps); block handles (b, h, 64-query tile).
// Warp w owns query rows [16w, 16w+16). S and O accumulators in registers.
// smem: sQ[64][68], sK[64][68], sP[64][68], sV[64][72] = 70656 B dynamic.
// ===========================================================================
#define ATT_SMEM ((3 * 64 * 68 + 64 * 72) * 4)

__global__ __launch_bounds__(128)
void attn_tc(const float* __restrict__ Q, const float* __restrict__ K,
             const float* __restrict__ V, float* __restrict__ O)
{
    extern __shared__ float sm[];
    float* sQ = sm;                  // [64][68] tf32
    float* sK = sm + 64 * 68;        // [64][68] tf32 (row-major [key][d])
    float* sP = sm + 2 * 64 * 68;    // [64][68] tf32 probs
    float* sV = sm + 3 * 64 * 68;    // [64][72] tf32 (row-major [key][d])

    const int tid = threadIdx.x;
    const int w = tid >> 5;
    const int lane = tid & 31;
    const int g = lane >> 2;
    const int t = lane & 3;
    const int qt = blockIdx.x;
    const int bh = blockIdx.y;
    const int b = bh >> 4, h = bh & 15;
    const int base = (b * NSEQ) * EMB + h * DH;
    const int qbase = qt * 64;

    const int r0 = w * 16 + g;       // local query row (first)
    const int r1 = r0 + 8;           // local query row (second)

    // Stage Q tile (tf32, row-major [q][d])
#pragma unroll
    for (int i = 0; i < 8; i++) {
        int idx = i * 128 + tid;
        int row = idx >> 4, c4 = idx & 15;
        float4 f = *(const float4*)&Q[base + (qbase + row) * EMB + c4 * 4];
        f.x = to_tf32(f.x); f.y = to_tf32(f.y);
        f.z = to_tf32(f.z); f.w = to_tf32(f.w);
        *(float4*)(sQ + row * 68 + c4 * 4) = f;
    }

    float o[8][4];
#pragma unroll
    for (int nf = 0; nf < 8; nf++)
#pragma unroll
        for (int q = 0; q < 4; q++) o[nf][q] = 0.f;
    float mr0 = -INFINITY, mr1 = -INFINITY;
    float lr0 = 0.f, lr1 = 0.f;

    for (int j = 0; j <= qt; j++) {
        __syncthreads();  // prior iter done with sK/sV/sP (also covers sQ store)

        // Stage K and V tiles (tf32)
#pragma unroll
        for (int i = 0; i < 8; i++) {
            int idx = i * 128 + tid;
            int row = idx >> 4, c4 = idx & 15;
            float4 fk = *(const float4*)&K[base + (j * 64 + row) * EMB + c4 * 4];
            float4 fv = *(const float4*)&V[base + (j * 64 + row) * EMB + c4 * 4];
            fk.x = to_tf32(fk.x); fk.y = to_tf32(fk.y);
            fk.z = to_tf32(fk.z); fk.w = to_tf32(fk.w);
            fv.x = to_tf32(fv.x); fv.y = to_tf32(fv.y);
            fv.z = to_tf32(fv.z); fv.w = to_tf32(fv.w);
            *(float4*)(sK + row * 68 + c4 * 4) = fk;
            *(float4*)(sV + row * 72 + c4 * 4) = fv;
        }
        __syncthreads();

        // ---- S = Q K^T (m16 x n64 x k64 per warp) ----
        float s[8][4];
#pragma unroll
        for (int nf = 0; nf < 8; nf++)
#pragma unroll
            for (int q = 0; q < 4; q++) s[nf][q] = 0.f;
#pragma unroll
        for (int kb8 = 0; kb8 < 8; kb8++) {
            const int kb = kb8 * 8;
            uint32_t a[4];
            {
                const float* bp = sQ + r0 * 68 + kb + t;
                a[0] = __float_as_uint(bp[0]);
                a[1] = __float_as_uint(bp[8 * 68]);
                a[2] = __float_as_uint(bp[4]);
                a[3] = __float_as_uint(bp[8 * 68 + 4]);
            }
#pragma unroll
            for (int nf = 0; nf < 8; nf++) {
                uint32_t bf[2];
                const float* bp = sK + (nf * 8 + g) * 68 + kb + t;
                bf[0] = __float_as_uint(bp[0]);
                bf[1] = __float_as_uint(bp[4]);
                mma_tf32(s[nf], a, bf);
            }
        }

        // ---- scale + causal mask ----
        const bool diag = (j == qt);
#pragma unroll
        for (int nf = 0; nf < 8; nf++) {
            const int c0 = nf * 8 + 2 * t;
            if (diag) {
                s[nf][0] = (c0 <= r0)     ? s[nf][0] * SCALE : -1e30f;
                s[nf][1] = (c0 + 1 <= r0) ? s[nf][1] * SCALE : -1e30f;
                s[nf][2] = (c0 <= r1)     ? s[nf][2] * SCALE : -1e30f;
                s[nf][3] = (c0 + 1 <= r1) ? s[nf][3] * SCALE : -1e30f;
            } else {
                s[nf][0] *= SCALE; s[nf][1] *= SCALE;
                s[nf][2] *= SCALE; s[nf][3] *= SCALE;
            }
        }

        // ---- online softmax (registers) ----
        float mt0 = -INFINITY, mt1 = -INFINITY;
#pragma unroll
        for (int nf = 0; nf < 8; nf++) {
            mt0 = fmaxf(mt0, fmaxf(s[nf][0], s[nf][1]));
            mt1 = fmaxf(mt1, fmaxf(s[nf][2], s[nf][3]));
        }
        mt0 = fmaxf(mt0, __shfl_xor_sync(0xffffffffu, mt0, 1));
        mt0 = fmaxf(mt0, __shfl_xor_sync(0xffffffffu, mt0, 2));
        mt1 = fmaxf(mt1, __shfl_xor_sync(0xffffffffu, mt1, 1));
        mt1 = fmaxf(mt1, __shfl_xor_sync(0xffffffffu, mt1, 2));
        const float mn0 = fmaxf(mr0, mt0);
        const float mn1 = fmaxf(mr1, mt1);
        const float al0 = __expf(mr0 - mn0);
        const float al1 = __expf(mr1 - mn1);
        float sum0 = 0.f, sum1 = 0.f;
#pragma unroll
        for (int nf = 0; nf < 8; nf++) {
            s[nf][0] = __expf(s[nf][0] - mn0);
            s[nf][1] = __expf(s[nf][1] - mn0);
            s[nf][2] = __expf(s[nf][2] - mn1);
            s[nf][3] = __expf(s[nf][3] - mn1);
            sum0 += s[nf][0] + s[nf][1];
            sum1 += s[nf][2] + s[nf][3];
        }
        sum0 += __shfl_xor_sync(0xffffffffu, sum0, 1);
        sum0 += __shfl_xor_sync(0xffffffffu, sum0, 2);
        sum1 += __shfl_xor_sync(0xffffffffu, sum1, 1);
        sum1 += __shfl_xor_sync(0xffffffffu, sum1, 2);
        lr0 = lr0 * al0 + sum0;
        lr1 = lr1 * al1 + sum1;
        mr0 = mn0; mr1 = mn1;
#pragma unroll
        for (int nf = 0; nf < 8; nf++) {
            o[nf][0] *= al0; o[nf][1] *= al0;
            o[nf][2] *= al1; o[nf][3] *= al1;
        }

        // ---- write P to smem (tf32) ----
#pragma unroll
        for (int nf = 0; nf < 8; nf++) {
            const int c0 = nf * 8 + 2 * t;
            float2 p0, p1;
            p0.x = to_tf32(s[nf][0]); p0.y = to_tf32(s[nf][1]);
            p1.x = to_tf32(s[nf][2]); p1.y = to_tf32(s[nf][3]);
            *(float2*)(sP + r0 * 68 + c0) = p0;
            *(float2*)(sP + r1 * 68 + c0) = p1;
        }
        __syncwarp();
        __syncthreads();  // sP visible to the whole block? (each warp only reads
                          // its own rows, but keep full sync for safety/order)

        // ---- O += P @ V (m16 x n64(d) x k64(keys)) ----
#pragma unroll
        for (int kb8 = 0; kb8 < 8; kb8++) {
            const int kb = kb8 * 8;
            uint32_t a[4];
            {
                const float* bp = sP + r0 * 68 + kb + t;
                a[0] = __float_as_uint(bp[0]);
                a[1] = __float_as_uint(bp[8 * 68]);
                a[2] = __float_as_uint(bp[4]);
                a[3] = __float_as_uint(bp[8 * 68 + 4]);
            }
#pragma unroll
            for (int nf = 0; nf < 8; nf++) {
                uint32_t bf[2];
                bf[0] = __float_as_uint(sV[(kb + t) * 72 + nf * 8 + g]);
                bf[1] = __float_as_uint(sV[(kb + t + 4) * 72 + nf * 8 + g]);
                mma_tf32(o[nf], a, bf);
            }
        }
    }

    // ---- epilogue: normalize, store ctx [B,N,E] ----
    const float inv0 = 1.f / lr0;
    const float inv1 = 1.f / lr1;
#pragma unroll
    for (int nf = 0; nf < 8; nf++) {
        const int c0 = nf * 8 + 2 * t;
        float2 v0, v1;
        v0.x = o[nf][0] * inv0; v0.y = o[nf][1] * inv0;
        v1.x = o[nf][2] * inv1; v1.y = o[nf][3] * inv1;
        *(float2*)&O[base + (qbase + r0) * EMB + c0] = v0;
        *(float2*)&O[base + (qbase + r1) * EMB + c0] = v1;
    }
}

// ---------------------------------------------------------------------------
extern "C" void kernel_launch(void* const* d_in, const int* in_sizes, int n_in,
                              void* d_out, int out_size)
{
    const float* xq = (const float*)d_in[0];
    const float* xk = (const float*)d_in[1];
    const float* xv = (const float*)d_in[2];
    // d_in[3] = attn_mask (causal triu) — implemented analytically, ignored
    const float* Wq = (const float*)d_in[4];
    const float* Wk = (const float*)d_in[5];
    const float* Wv = (const float*)d_in[6];
    const float* Wo = (const float*)d_in[7];
    const float* bo = (const float*)d_in[8];
    float* out = (float*)d_out;

    float *q, *k, *v, *c;
    cudaGetSymbolAddress((void**)&q, g_Q);
    cudaGetSymbolAddress((void**)&k, g_K);
    cudaGetSymbolAddress((void**)&v, g_V);
    cudaGetSymbolAddress((void**)&c, g_C);

    const int M = BSZ * NSEQ;
    cudaFuncSetAttribute(attn_tc, cudaFuncAttributeMaxDynamicSharedMemorySize,
                         ATT_SMEM);

    dim3 gg(EMB / 128, M / 128);  // (8, 64)
    gemm_tc<false><<<gg, 256>>>(xq, Wq, nullptr, q, M, EMB, EMB);
    gemm_tc<false><<<gg, 256>>>(xk, Wk, nullptr, k, M, EMB, EMB);
    gemm_tc<false><<<gg, 256>>>(xv, Wv, nullptr, v, M, EMB, EMB);

    attn_tc<<<dim3(NSEQ / 64, BSZ * HNUM), 128, ATT_SMEM>>>(q, k, v, c);

    gemm_tc<true><<<gg, 256>>>(c, Wo, bo, out, M, EMB, EMB);
}

// round 7
// speedup vs baseline: 3.9411x; 2.1602x over previous
#include <cuda_runtime.h>
#include <cuda_bf16.h>
#include <cstdint>
#include <math.h>

#define BSZ  4
#define NSEQ 2048
#define EMB  1024
#define HNUM 16
#define DH   64
#define SCALE 0.125f  // 1/sqrt(64)

// Scratch (device globals — no allocation allowed)
__device__ float g_Q[BSZ * NSEQ * EMB];
__device__ float g_K[BSZ * NSEQ * EMB];
__device__ float g_V[BSZ * NSEQ * EMB];
__device__ float g_C[BSZ * NSEQ * EMB];

__device__ __forceinline__ float to_tf32(float x) {
    float r;
    asm("cvt.rna.tf32.f32 %0, %1;" : "=f"(r) : "f"(x));
    return r;
}

__device__ __forceinline__ void mma_tf32(float* d, const uint32_t* a, const uint32_t* b) {
    asm volatile(
        "mma.sync.aligned.m16n8k8.row.col.f32.tf32.tf32.f32 "
        "{%0,%1,%2,%3}, {%4,%5,%6,%7}, {%8,%9}, {%0,%1,%2,%3};"
        : "+f"(d[0]), "+f"(d[1]), "+f"(d[2]), "+f"(d[3])
        : "r"(a[0]), "r"(a[1]), "r"(a[2]), "r"(a[3]), "r"(b[0]), "r"(b[1]));
}

__device__ __forceinline__ void mma_bf16(float* d, const uint32_t* a, const uint32_t* b) {
    asm volatile(
        "mma.sync.aligned.m16n8k16.row.col.f32.bf16.bf16.f32 "
        "{%0,%1,%2,%3}, {%4,%5,%6,%7}, {%8,%9}, {%0,%1,%2,%3};"
        : "+f"(d[0]), "+f"(d[1]), "+f"(d[2]), "+f"(d[3])
        : "r"(a[0]), "r"(a[1]), "r"(a[2]), "r"(a[3]), "r"(b[0]), "r"(b[1]));
}

// Split f0,f1 into packed bf16x2 hi and lo words.
__device__ __forceinline__ void split2(float f0, float f1, uint32_t& hi, uint32_t& lo) {
    __nv_bfloat16 h0 = __float2bfloat16_rn(f0);
    __nv_bfloat16 h1 = __float2bfloat16_rn(f1);
    float r0 = f0 - __bfloat162float(h0);
    float r1 = f1 - __bfloat162float(h1);
    __nv_bfloat16 l0 = __float2bfloat16_rn(r0);
    __nv_bfloat16 l1 = __float2bfloat16_rn(r1);
    hi = (uint32_t)__bfloat16_as_ushort(h0) | ((uint32_t)__bfloat16_as_ushort(h1) << 16);
    lo = (uint32_t)__bfloat16_as_ushort(l0) | ((uint32_t)__bfloat16_as_ushort(l1) << 16);
}

// ===========================================================================
// bf16x2-split GEMM (3 MMAs per k16): C = A[M,K] @ W[Ncol,K]^T (+bias).
// CTA 128x128, BK=32, 256 threads = 8 warps (4M x 2N), warp tile 32x64.
// hi/lo bf16 tiles staged in smem; pitch 20 u32 (40 bf16) => conflict-free.
// ===========================================================================
#define BKG 32
#define GP 20   // tile pitch in uint32 units (40 bf16 = 80B)

template <bool BIAS>
__device__ __forceinline__
void gemm_bf3_body(const float* __restrict__ A, const float* __restrict__ W,
                   const float* __restrict__ bias, float* __restrict__ C,
                   int M, int Ncol, int K)
{
    __shared__ uint32_t sAh[128 * GP];
    __shared__ uint32_t sAl[128 * GP];
    __shared__ uint32_t sBh[128 * GP];
    __shared__ uint32_t sBl[128 * GP];

    const int tid = threadIdx.x;
    const int wid = tid >> 5;
    const int lane = tid & 31;
    const int g = lane >> 2;
    const int t = lane & 3;
    const int wm = wid >> 1;        // 0..3 (M dir)
    const int wn = wid & 1;         // 0..1 (N dir)
    const int m0 = blockIdx.y * 128;
    const int n0 = blockIdx.x * 128;

    float d[2][8][4];
#pragma unroll
    for (int i = 0; i < 2; i++)
#pragma unroll
        for (int j = 0; j < 8; j++)
#pragma unroll
            for (int q = 0; q < 4; q++) d[i][j][q] = 0.f;

    const int nchunks = K / BKG;
    for (int c = 0; c < nchunks; ++c) {
        const int k0 = c * BKG;
        // ---- Stage A, B chunk: split into bf16 hi/lo tiles ----
#pragma unroll
        for (int i = 0; i < 4; i++) {
            int idx = i * 256 + tid;        // 0..1023
            int row = idx >> 3;             // 0..127
            int c4  = idx & 7;              // 0..7 (float4 index within 32-k row)
            float4 fa = *(const float4*)&A[(size_t)(m0 + row) * K + k0 + c4 * 4];
            float4 fb = *(const float4*)&W[(size_t)(n0 + row) * K + k0 + c4 * 4];
            uint32_t h0, l0, h1, l1;
            split2(fa.x, fa.y, h0, l0);
            split2(fa.z, fa.w, h1, l1);
            const int off = row * GP + c4 * 2;
            sAh[off] = h0; sAh[off + 1] = h1;
            sAl[off] = l0; sAl[off + 1] = l1;
            split2(fb.x, fb.y, h0, l0);
            split2(fb.z, fb.w, h1, l1);
            sBh[off] = h0; sBh[off + 1] = h1;
            sBl[off] = l0; sBl[off + 1] = l1;
        }
        __syncthreads();

        // ---- Compute: 2 k16-steps ----
#pragma unroll
        for (int ks = 0; ks < 2; ks++) {
            const int kb = ks * 8;          // u32 offset within row
            uint32_t ah[2][4], al[2][4];
#pragma unroll
            for (int mf = 0; mf < 2; mf++) {
                const int roff = (wm * 32 + mf * 16 + g) * GP + kb + t;
                ah[mf][0] = sAh[roff];
                ah[mf][1] = sAh[roff + 8 * GP];
                ah[mf][2] = sAh[roff + 4];
                ah[mf][3] = sAh[roff + 8 * GP + 4];
                al[mf][0] = sAl[roff];
                al[mf][1] = sAl[roff + 8 * GP];
                al[mf][2] = sAl[roff + 4];
                al[mf][3] = sAl[roff + 8 * GP + 4];
            }
#pragma unroll
            for (int half = 0; half < 2; half++) {
                uint32_t bh_[4][2], bl_[4][2];
#pragma unroll
                for (int nh = 0; nh < 4; nh++) {
                    const int nf = half * 4 + nh;
                    const int coff = (wn * 64 + nf * 8 + g) * GP + kb + t;
                    bh_[nh][0] = sBh[coff];
                    bh_[nh][1] = sBh[coff + 4];
                    bl_[nh][0] = sBl[coff];
                    bl_[nh][1] = sBl[coff + 4];
                }
#pragma unroll
                for (int mf = 0; mf < 2; mf++)
#pragma unroll
                    for (int nh = 0; nh < 4; nh++) {
                        const int nf = half * 4 + nh;
                        mma_bf16(d[mf][nf], ah[mf], bh_[nh]);
                        mma_bf16(d[mf][nf], ah[mf], bl_[nh]);
                        mma_bf16(d[mf][nf], al[mf], bh_[nh]);
                    }
            }
        }
        __syncthreads();
    }

    // ---- Epilogue ----
#pragma unroll
    for (int mf = 0; mf < 2; mf++) {
        const int r0 = m0 + wm * 32 + mf * 16 + g;
#pragma unroll
        for (int nf = 0; nf < 8; nf++) {
            const int col = n0 + wn * 64 + nf * 8 + 2 * t;
            float2 v0, v1;
            v0.x = d[mf][nf][0]; v0.y = d[mf][nf][1];
            v1.x = d[mf][nf][2]; v1.y = d[mf][nf][3];
            if (BIAS) {
                const float2 bv = *(const float2*)&bias[col];
                v0.x += bv.x; v0.y += bv.y;
                v1.x += bv.x; v1.y += bv.y;
            }
            *(float2*)&C[(size_t)r0 * Ncol + col] = v0;
            *(float2*)&C[(size_t)(r0 + 8) * Ncol + col] = v1;
        }
    }
}

// Fused Q/K/V projection: blockIdx.z selects which GEMM.
__global__ __launch_bounds__(256)
void qkv_gemm(const float* __restrict__ xq, const float* __restrict__ xk,
              const float* __restrict__ xv, const float* __restrict__ Wq,
              const float* __restrict__ Wk, const float* __restrict__ Wv,
              float* __restrict__ q, float* __restrict__ k, float* __restrict__ v)
{
    const int z = blockIdx.z;
    const float* A = (z == 0) ? xq : (z == 1) ? xk : xv;
    const float* W = (z == 0) ? Wq : (z == 1) ? Wk : Wv;
    float* C       = (z == 0) ? q  : (z == 1) ? k  : v;
    gemm_bf3_body<false>(A, W, nullptr, C, BSZ * NSEQ, EMB, EMB);
}

__global__ __launch_bounds__(256)
void out_gemm(const float* __restrict__ A, const float* __restrict__ W,
              const float* __restrict__ bias, float* __restrict__ C)
{
    gemm_bf3_body<true>(A, W, bias, C, BSZ * NSEQ, EMB, EMB);
}

// ===========================================================================
// Tensor-core flash attention (causal), tf32 HMMA — unchanged from R6.
// ===========================================================================
#define ATT_SMEM ((3 * 64 * 68 + 64 * 72) * 4)

__global__ __launch_bounds__(128)
void attn_tc(const float* __restrict__ Q, const float* __restrict__ K,
             const float* __restrict__ V, float* __restrict__ O)
{
    extern __shared__ float sm[];
    float* sQ = sm;                  // [64][68] tf32
    float* sK = sm + 64 * 68;        // [64][68] tf32
    float* sP = sm + 2 * 64 * 68;    // [64][68] tf32 probs
    float* sV = sm + 3 * 64 * 68;    // [64][72] tf32

    const int tid = threadIdx.x;
    const int w = tid >> 5;
    const int lane = tid & 31;
    const int g = lane >> 2;
    const int t = lane & 3;
    const int qt = blockIdx.x;
    const int bh = blockIdx.y;
    const int b = bh >> 4, h = bh & 15;
    const int base = (b * NSEQ) * EMB + h * DH;
    const int qbase = qt * 64;

    const int r0 = w * 16 + g;
    const int r1 = r0 + 8;

#pragma unroll
    for (int i = 0; i < 8; i++) {
        int idx = i * 128 + tid;
        int row = idx >> 4, c4 = idx & 15;
        float4 f = *(const float4*)&Q[base + (qbase + row) * EMB + c4 * 4];
        f.x = to_tf32(f.x); f.y = to_tf32(f.y);
        f.z = to_tf32(f.z); f.w = to_tf32(f.w);
        *(float4*)(sQ + row * 68 + c4 * 4) = f;
    }

    float o[8][4];
#pragma unroll
    for (int nf = 0; nf < 8; nf++)
#pragma unroll
        for (int q = 0; q < 4; q++) o[nf][q] = 0.f;
    float mr0 = -INFINITY, mr1 = -INFINITY;
    float lr0 = 0.f, lr1 = 0.f;

    for (int j = 0; j <= qt; j++) {
        __syncthreads();

#pragma unroll
        for (int i = 0; i < 8; i++) {
            int idx = i * 128 + tid;
            int row = idx >> 4, c4 = idx & 15;
            float4 fk = *(const float4*)&K[base + (j * 64 + row) * EMB + c4 * 4];
            float4 fv = *(const float4*)&V[base + (j * 64 + row) * EMB + c4 * 4];
            fk.x = to_tf32(fk.x); fk.y = to_tf32(fk.y);
            fk.z = to_tf32(fk.z); fk.w = to_tf32(fk.w);
            fv.x = to_tf32(fv.x); fv.y = to_tf32(fv.y);
            fv.z = to_tf32(fv.z); fv.w = to_tf32(fv.w);
            *(float4*)(sK + row * 68 + c4 * 4) = fk;
            *(float4*)(sV + row * 72 + c4 * 4) = fv;
        }
        __syncthreads();

        float s[8][4];
#pragma unroll
        for (int nf = 0; nf < 8; nf++)
#pragma unroll
            for (int q = 0; q < 4; q++) s[nf][q] = 0.f;
#pragma unroll
        for (int kb8 = 0; kb8 < 8; kb8++) {
            const int kb = kb8 * 8;
            uint32_t a[4];
            {
                const float* bp = sQ + r0 * 68 + kb + t;
                a[0] = __float_as_uint(bp[0]);
                a[1] = __float_as_uint(bp[8 * 68]);
                a[2] = __float_as_uint(bp[4]);
                a[3] = __float_as_uint(bp[8 * 68 + 4]);
            }
#pragma unroll
            for (int nf = 0; nf < 8; nf++) {
                uint32_t bf[2];
                const float* bp = sK + (nf * 8 + g) * 68 + kb + t;
                bf[0] = __float_as_uint(bp[0]);
                bf[1] = __float_as_uint(bp[4]);
                mma_tf32(s[nf], a, bf);
            }
        }

        const bool diag = (j == qt);
#pragma unroll
        for (int nf = 0; nf < 8; nf++) {
            const int c0 = nf * 8 + 2 * t;
            if (diag) {
                s[nf][0] = (c0 <= r0)     ? s[nf][0] * SCALE : -1e30f;
                s[nf][1] = (c0 + 1 <= r0) ? s[nf][1] * SCALE : -1e30f;
                s[nf][2] = (c0 <= r1)     ? s[nf][2] * SCALE : -1e30f;
                s[nf][3] = (c0 + 1 <= r1) ? s[nf][3] * SCALE : -1e30f;
            } else {
                s[nf][0] *= SCALE; s[nf][1] *= SCALE;
                s[nf][2] *= SCALE; s[nf][3] *= SCALE;
            }
        }

        float mt0 = -INFINITY, mt1 = -INFINITY;
#pragma unroll
        for (int nf = 0; nf < 8; nf++) {
            mt0 = fmaxf(mt0, fmaxf(s[nf][0], s[nf][1]));
            mt1 = fmaxf(mt1, fmaxf(s[nf][2], s[nf][3]));
        }
        mt0 = fmaxf(mt0, __shfl_xor_sync(0xffffffffu, mt0, 1));
        mt0 = fmaxf(mt0, __shfl_xor_sync(0xffffffffu, mt0, 2));
        mt1 = fmaxf(mt1, __shfl_xor_sync(0xffffffffu, mt1, 1));
        mt1 = fmaxf(mt1, __shfl_xor_sync(0xffffffffu, mt1, 2));
        const float mn0 = fmaxf(mr0, mt0);
        const float mn1 = fmaxf(mr1, mt1);
        const float al0 = __expf(mr0 - mn0);
        const float al1 = __expf(mr1 - mn1);
        float sum0 = 0.f, sum1 = 0.f;
#pragma unroll
        for (int nf = 0; nf < 8; nf++) {
            s[nf][0] = __expf(s[nf][0] - mn0);
            s[nf][1] = __expf(s[nf][1] - mn0);
            s[nf][2] = __expf(s[nf][2] - mn1);
            s[nf][3] = __expf(s[nf][3] - mn1);
            sum0 += s[nf][0] + s[nf][1];
            sum1 += s[nf][2] + s[nf][3];
        }
        sum0 += __shfl_xor_sync(0xffffffffu, sum0, 1);
        sum0 += __shfl_xor_sync(0xffffffffu, sum0, 2);
        sum1 += __shfl_xor_sync(0xffffffffu, sum1, 1);
        sum1 += __shfl_xor_sync(0xffffffffu, sum1, 2);
        lr0 = lr0 * al0 + sum0;
        lr1 = lr1 * al1 + sum1;
        mr0 = mn0; mr1 = mn1;
#pragma unroll
        for (int nf = 0; nf < 8; nf++) {
            o[nf][0] *= al0; o[nf][1] *= al0;
            o[nf][2] *= al1; o[nf][3] *= al1;
        }

#pragma unroll
        for (int nf = 0; nf < 8; nf++) {
            const int c0 = nf * 8 + 2 * t;
            float2 p0, p1;
            p0.x = to_tf32(s[nf][0]); p0.y = to_tf32(s[nf][1]);
            p1.x = to_tf32(s[nf][2]); p1.y = to_tf32(s[nf][3]);
            *(float2*)(sP + r0 * 68 + c0) = p0;
            *(float2*)(sP + r1 * 68 + c0) = p1;
        }
        __syncwarp();
        __syncthreads();

#pragma unroll
        for (int kb8 = 0; kb8 < 8; kb8++) {
            const int kb = kb8 * 8;
            uint32_t a[4];
            {
                const float* bp = sP + r0 * 68 + kb + t;
                a[0] = __float_as_uint(bp[0]);
                a[1] = __float_as_uint(bp[8 * 68]);
                a[2] = __float_as_uint(bp[4]);
                a[3] = __float_as_uint(bp[8 * 68 + 4]);
            }
#pragma unroll
            for (int nf = 0; nf < 8; nf++) {
                uint32_t bf[2];
                bf[0] = __float_as_uint(sV[(kb + t) * 72 + nf * 8 + g]);
                bf[1] = __float_as_uint(sV[(kb + t + 4) * 72 + nf * 8 + g]);
                mma_tf32(o[nf], a, bf);
            }
        }
    }

    const float inv0 = 1.f / lr0;
    const float inv1 = 1.f / lr1;
#pragma unroll
    for (int nf = 0; nf < 8; nf++) {
        const int c0 = nf * 8 + 2 * t;
        float2 v0, v1;
        v0.x = o[nf][0] * inv0; v0.y = o[nf][1] * inv0;
        v1.x = o[nf][2] * inv1; v1.y = o[nf][3] * inv1;
        *(float2*)&O[base + (qbase + r0) * EMB + c0] = v0;
        *(float2*)&O[base + (qbase + r1) * EMB + c0] = v1;
    }
}

// ---------------------------------------------------------------------------
extern "C" void kernel_launch(void* const* d_in, const int* in_sizes, int n_in,
                              void* d_out, int out_size)
{
    const float* xq = (const float*)d_in[0];
    const float* xk = (const float*)d_in[1];
    const float* xv = (const float*)d_in[2];
    // d_in[3] = attn_mask (causal triu) — implemented analytically, ignored
    const float* Wq = (const float*)d_in[4];
    const float* Wk = (const float*)d_in[5];
    const float* Wv = (const float*)d_in[6];
    const float* Wo = (const float*)d_in[7];
    const float* bo = (const float*)d_in[8];
    float* out = (float*)d_out;

    float *q, *k, *v, *c;
    cudaGetSymbolAddress((void**)&q, g_Q);
    cudaGetSymbolAddress((void**)&k, g_K);
    cudaGetSymbolAddress((void**)&v, g_V);
    cudaGetSymbolAddress((void**)&c, g_C);

    cudaFuncSetAttribute(attn_tc, cudaFuncAttributeMaxDynamicSharedMemorySize,
                         ATT_SMEM);

    dim3 gqkv(EMB / 128, (BSZ * NSEQ) / 128, 3);  // (8, 64, 3)
    qkv_gemm<<<gqkv, 256>>>(xq, xk, xv, Wq, Wk, Wv, q, k, v);

    attn_tc<<<dim3(NSEQ / 64, BSZ * HNUM), 128, ATT_SMEM>>>(q, k, v, c);

    out_gemm<<<dim3(EMB / 128, (BSZ * NSEQ) / 128), 256>>>(c, Wo, bo, out);
}

// round 8
// speedup vs baseline: 4.5819x; 1.1626x over previous
#include <cuda_runtime.h>
#include <cuda_bf16.h>
#include <cstdint>
#include <math.h>

#define BSZ  4
#define NSEQ 2048
#define EMB  1024
#define HNUM 16
#define DH   64
#define SCALE 0.125f  // 1/sqrt(64)

// Scratch (device globals — no allocation allowed)
__device__ float g_Q[BSZ * NSEQ * EMB];
__device__ float g_K[BSZ * NSEQ * EMB];
__device__ float g_V[BSZ * NSEQ * EMB];
__device__ float g_C[BSZ * NSEQ * EMB];

__device__ __forceinline__ float to_tf32(float x) {
    float r;
    asm("cvt.rna.tf32.f32 %0, %1;" : "=f"(r) : "f"(x));
    return r;
}

__device__ __forceinline__ void mma_tf32(float* d, const uint32_t* a, const uint32_t* b) {
    asm volatile(
        "mma.sync.aligned.m16n8k8.row.col.f32.tf32.tf32.f32 "
        "{%0,%1,%2,%3}, {%4,%5,%6,%7}, {%8,%9}, {%0,%1,%2,%3};"
        : "+f"(d[0]), "+f"(d[1]), "+f"(d[2]), "+f"(d[3])
        : "r"(a[0]), "r"(a[1]), "r"(a[2]), "r"(a[3]), "r"(b[0]), "r"(b[1]));
}

__device__ __forceinline__ void mma_bf16(float* d, const uint32_t* a, const uint32_t* b) {
    asm volatile(
        "mma.sync.aligned.m16n8k16.row.col.f32.bf16.bf16.f32 "
        "{%0,%1,%2,%3}, {%4,%5,%6,%7}, {%8,%9}, {%0,%1,%2,%3};"
        : "+f"(d[0]), "+f"(d[1]), "+f"(d[2]), "+f"(d[3])
        : "r"(a[0]), "r"(a[1]), "r"(a[2]), "r"(a[3]), "r"(b[0]), "r"(b[1]));
}

// Split f0,f1 into packed bf16x2 hi and lo words.
__device__ __forceinline__ void split2(float f0, float f1, uint32_t& hi, uint32_t& lo) {
    __nv_bfloat16 h0 = __float2bfloat16_rn(f0);
    __nv_bfloat16 h1 = __float2bfloat16_rn(f1);
    float r0 = f0 - __bfloat162float(h0);
    float r1 = f1 - __bfloat162float(h1);
    __nv_bfloat16 l0 = __float2bfloat16_rn(r0);
    __nv_bfloat16 l1 = __float2bfloat16_rn(r1);
    hi = (uint32_t)__bfloat16_as_ushort(h0) | ((uint32_t)__bfloat16_as_ushort(h1) << 16);
    lo = (uint32_t)__bfloat16_as_ushort(l0) | ((uint32_t)__bfloat16_as_ushort(l1) << 16);
}

// ===========================================================================
// bf16x2-split GEMM (3 MMAs per k16), software-pipelined:
//   - register prefetch of next chunk's global loads (LDG hidden under MMAs)
//   - double-buffered hi/lo smem tiles, ONE __syncthreads per chunk
// CTA 128x128, BK=32, 256 threads = 8 warps (4M x 2N), warp tile 32x64.
// pitch 20 u32 (40 bf16) => conflict-free fragment LDS.
// ===========================================================================
#define BKG 32
#define GP 20                       // tile pitch in uint32 units
#define GBUF (128 * GP)             // one buffer, in u32
#define GEMM_SMEM (8 * GBUF * 4)    // 8 buffers total (A/B x hi/lo x 2), bytes

template <bool BIAS>
__device__ __forceinline__
void gemm_bf3_body(const float* __restrict__ A, const float* __restrict__ W,
                   const float* __restrict__ bias, float* __restrict__ C,
                   int M, int Ncol, int K)
{
    extern __shared__ uint32_t su[];
    uint32_t* const sAh = su;
    uint32_t* const sAl = su + 2 * GBUF;
    uint32_t* const sBh = su + 4 * GBUF;
    uint32_t* const sBl = su + 6 * GBUF;

    const int tid = threadIdx.x;
    const int wid = tid >> 5;
    const int lane = tid & 31;
    const int g = lane >> 2;
    const int t = lane & 3;
    const int wm = wid >> 1;        // 0..3 (M dir)
    const int wn = wid & 1;         // 0..1 (N dir)
    const int m0 = blockIdx.y * 128;
    const int n0 = blockIdx.x * 128;

    // Load mapping: thread covers rows {i*32 + (tid>>3)}, float4 col tid&7.
    const int c4 = tid & 7;
    const int rowb = tid >> 3;
    const float* Ap = A + (size_t)(m0 + rowb) * K + c4 * 4;
    const float* Wp = W + (size_t)(n0 + rowb) * K + c4 * 4;

    float d[2][8][4];
#pragma unroll
    for (int i = 0; i < 2; i++)
#pragma unroll
        for (int j = 0; j < 8; j++)
#pragma unroll
            for (int q = 0; q < 4; q++) d[i][j][q] = 0.f;

    float4 pa[4], pb[4];

#define LOAD_CHUNK(cc) do {                                              \
    const int _k0 = (cc) * BKG;                                          \
    _Pragma("unroll")                                                    \
    for (int i = 0; i < 4; i++) {                                        \
        pa[i] = *(const float4*)(Ap + (size_t)i * 32 * K + _k0);         \
        pb[i] = *(const float4*)(Wp + (size_t)i * 32 * K + _k0);         \
    }                                                                    \
} while (0)

#define STORE_CHUNK(bb) do {                                             \
    uint32_t* _ah = sAh + (bb) * GBUF;                                   \
    uint32_t* _al = sAl + (bb) * GBUF;                                   \
    uint32_t* _bh = sBh + (bb) * GBUF;                                   \
    uint32_t* _bl = sBl + (bb) * GBUF;                                   \
    _Pragma("unroll")                                                    \
    for (int i = 0; i < 4; i++) {                                        \
        const int off = (i * 32 + rowb) * GP + c4 * 2;                   \
        uint32_t h0, l0, h1, l1;                                         \
        split2(pa[i].x, pa[i].y, h0, l0);                                \
        split2(pa[i].z, pa[i].w, h1, l1);                                \
        _ah[off] = h0; _ah[off + 1] = h1;                                \
        _al[off] = l0; _al[off + 1] = l1;                                \
        split2(pb[i].x, pb[i].y, h0, l0);                                \
        split2(pb[i].z, pb[i].w, h1, l1);                                \
        _bh[off] = h0; _bh[off + 1] = h1;                                \
        _bl[off] = l0; _bl[off + 1] = l1;                                \
    }                                                                    \
} while (0)

    const int nchunks = K / BKG;
    LOAD_CHUNK(0);
    STORE_CHUNK(0);
    __syncthreads();

    for (int c = 0; c < nchunks; ++c) {
        const bool more = (c + 1 < nchunks);
        if (more) LOAD_CHUNK(c + 1);

        const uint32_t* bAh = sAh + (c & 1) * GBUF;
        const uint32_t* bAl = sAl + (c & 1) * GBUF;
        const uint32_t* bBh = sBh + (c & 1) * GBUF;
        const uint32_t* bBl = sBl + (c & 1) * GBUF;

#pragma unroll
        for (int ks = 0; ks < 2; ks++) {
            const int kb = ks * 8;
            uint32_t ah[2][4], al[2][4];
#pragma unroll
            for (int mf = 0; mf < 2; mf++) {
                const int roff = (wm * 32 + mf * 16 + g) * GP + kb + t;
                ah[mf][0] = bAh[roff];
                ah[mf][1] = bAh[roff + 8 * GP];
                ah[mf][2] = bAh[roff + 4];
                ah[mf][3] = bAh[roff + 8 * GP + 4];
                al[mf][0] = bAl[roff];
                al[mf][1] = bAl[roff + 8 * GP];
                al[mf][2] = bAl[roff + 4];
                al[mf][3] = bAl[roff + 8 * GP + 4];
            }
#pragma unroll
            for (int half = 0; half < 2; half++) {
                uint32_t bh_[4][2], bl_[4][2];
#pragma unroll
                for (int nh = 0; nh < 4; nh++) {
                    const int nf = half * 4 + nh;
                    const int coff = (wn * 64 + nf * 8 + g) * GP + kb + t;
                    bh_[nh][0] = bBh[coff];
                    bh_[nh][1] = bBh[coff + 4];
                    bl_[nh][0] = bBl[coff];
                    bl_[nh][1] = bBl[coff + 4];
                }
#pragma unroll
                for (int mf = 0; mf < 2; mf++)
#pragma unroll
                    for (int nh = 0; nh < 4; nh++) {
                        const int nf = half * 4 + nh;
                        mma_bf16(d[mf][nf], ah[mf], bh_[nh]);
                        mma_bf16(d[mf][nf], ah[mf], bl_[nh]);
                        mma_bf16(d[mf][nf], al[mf], bh_[nh]);
                    }
            }
        }

        if (more) STORE_CHUNK((c + 1) & 1);
        __syncthreads();
    }

#undef LOAD_CHUNK
#undef STORE_CHUNK

    // ---- Epilogue ----
#pragma unroll
    for (int mf = 0; mf < 2; mf++) {
        const int r0 = m0 + wm * 32 + mf * 16 + g;
#pragma unroll
        for (int nf = 0; nf < 8; nf++) {
            const int col = n0 + wn * 64 + nf * 8 + 2 * t;
            float2 v0, v1;
            v0.x = d[mf][nf][0]; v0.y = d[mf][nf][1];
            v1.x = d[mf][nf][2]; v1.y = d[mf][nf][3];
            if (BIAS) {
                const float2 bv = *(const float2*)&bias[col];
                v0.x += bv.x; v0.y += bv.y;
                v1.x += bv.x; v1.y += bv.y;
            }
            *(float2*)&C[(size_t)r0 * Ncol + col] = v0;
            *(float2*)&C[(size_t)(r0 + 8) * Ncol + col] = v1;
        }
    }
}

// Fused Q/K/V projection: blockIdx.z selects which GEMM.
__global__ __launch_bounds__(256)
void qkv_gemm(const float* __restrict__ xq, const float* __restrict__ xk,
              const float* __restrict__ xv, const float* __restrict__ Wq,
              const float* __restrict__ Wk, const float* __restrict__ Wv,
              float* __restrict__ q, float* __restrict__ k, float* __restrict__ v)
{
    const int z = blockIdx.z;
    const float* A = (z == 0) ? xq : (z == 1) ? xk : xv;
    const float* W = (z == 0) ? Wq : (z == 1) ? Wk : Wv;
    float* C       = (z == 0) ? q  : (z == 1) ? k  : v;
    gemm_bf3_body<false>(A, W, nullptr, C, BSZ * NSEQ, EMB, EMB);
}

__global__ __launch_bounds__(256)
void out_gemm(const float* __restrict__ A, const float* __restrict__ W,
              const float* __restrict__ bias, float* __restrict__ C)
{
    gemm_bf3_body<true>(A, W, bias, C, BSZ * NSEQ, EMB, EMB);
}

// ===========================================================================
// Tensor-core flash attention (causal), tf32 HMMA — unchanged from R7.
// ===========================================================================
#define ATT_SMEM ((3 * 64 * 68 + 64 * 72) * 4)

__global__ __launch_bounds__(128)
void attn_tc(const float* __restrict__ Q, const float* __restrict__ K,
             const float* __restrict__ V, float* __restrict__ O)
{
    extern __shared__ float sm[];
    float* sQ = sm;                  // [64][68] tf32
    float* sK = sm + 64 * 68;        // [64][68] tf32
    float* sP = sm + 2 * 64 * 68;    // [64][68] tf32 probs
    float* sV = sm + 3 * 64 * 68;    // [64][72] tf32

    const int tid = threadIdx.x;
    const int w = tid >> 5;
    const int lane = tid & 31;
    const int g = lane >> 2;
    const int t = lane & 3;
    const int qt = blockIdx.x;
    const int bh = blockIdx.y;
    const int b = bh >> 4, h = bh & 15;
    const int base = (b * NSEQ) * EMB + h * DH;
    const int qbase = qt * 64;

    const int r0 = w * 16 + g;
    const int r1 = r0 + 8;

#pragma unroll
    for (int i = 0; i < 8; i++) {
        int idx = i * 128 + tid;
        int row = idx >> 4, c4 = idx & 15;
        float4 f = *(const float4*)&Q[base + (qbase + row) * EMB + c4 * 4];
        f.x = to_tf32(f.x); f.y = to_tf32(f.y);
        f.z = to_tf32(f.z); f.w = to_tf32(f.w);
        *(float4*)(sQ + row * 68 + c4 * 4) = f;
    }

    float o[8][4];
#pragma unroll
    for (int nf = 0; nf < 8; nf++)
#pragma unroll
        for (int q = 0; q < 4; q++) o[nf][q] = 0.f;
    float mr0 = -INFINITY, mr1 = -INFINITY;
    float lr0 = 0.f, lr1 = 0.f;

    for (int j = 0; j <= qt; j++) {
        __syncthreads();

#pragma unroll
        for (int i = 0; i < 8; i++) {
            int idx = i * 128 + tid;
            int row = idx >> 4, c4 = idx & 15;
            float4 fk = *(const float4*)&K[base + (j * 64 + row) * EMB + c4 * 4];
            float4 fv = *(const float4*)&V[base + (j * 64 + row) * EMB + c4 * 4];
            fk.x = to_tf32(fk.x); fk.y = to_tf32(fk.y);
            fk.z = to_tf32(fk.z); fk.w = to_tf32(fk.w);
            fv.x = to_tf32(fv.x); fv.y = to_tf32(fv.y);
            fv.z = to_tf32(fv.z); fv.w = to_tf32(fv.w);
            *(float4*)(sK + row * 68 + c4 * 4) = fk;
            *(float4*)(sV + row * 72 + c4 * 4) = fv;
        }
        __syncthreads();

        float s[8][4];
#pragma unroll
        for (int nf = 0; nf < 8; nf++)
#pragma unroll
            for (int q = 0; q < 4; q++) s[nf][q] = 0.f;
#pragma unroll
        for (int kb8 = 0; kb8 < 8; kb8++) {
            const int kb = kb8 * 8;
            uint32_t a[4];
            {
                const float* bp = sQ + r0 * 68 + kb + t;
                a[0] = __float_as_uint(bp[0]);
                a[1] = __float_as_uint(bp[8 * 68]);
                a[2] = __float_as_uint(bp[4]);
                a[3] = __float_as_uint(bp[8 * 68 + 4]);
            }
#pragma unroll
            for (int nf = 0; nf < 8; nf++) {
                uint32_t bf[2];
                const float* bp = sK + (nf * 8 + g) * 68 + kb + t;
                bf[0] = __float_as_uint(bp[0]);
                bf[1] = __float_as_uint(bp[4]);
                mma_tf32(s[nf], a, bf);
            }
        }

        const bool diag = (j == qt);
#pragma unroll
        for (int nf = 0; nf < 8; nf++) {
            const int c0 = nf * 8 + 2 * t;
            if (diag) {
                s[nf][0] = (c0 <= r0)     ? s[nf][0] * SCALE : -1e30f;
                s[nf][1] = (c0 + 1 <= r0) ? s[nf][1] * SCALE : -1e30f;
                s[nf][2] = (c0 <= r1)     ? s[nf][2] * SCALE : -1e30f;
                s[nf][3] = (c0 + 1 <= r1) ? s[nf][3] * SCALE : -1e30f;
            } else {
                s[nf][0] *= SCALE; s[nf][1] *= SCALE;
                s[nf][2] *= SCALE; s[nf][3] *= SCALE;
            }
        }

        float mt0 = -INFINITY, mt1 = -INFINITY;
#pragma unroll
        for (int nf = 0; nf < 8; nf++) {
            mt0 = fmaxf(mt0, fmaxf(s[nf][0], s[nf][1]));
            mt1 = fmaxf(mt1, fmaxf(s[nf][2], s[nf][3]));
        }
        mt0 = fmaxf(mt0, __shfl_xor_sync(0xffffffffu, mt0, 1));
        mt0 = fmaxf(mt0, __shfl_xor_sync(0xffffffffu, mt0, 2));
        mt1 = fmaxf(mt1, __shfl_xor_sync(0xffffffffu, mt1, 1));
        mt1 = fmaxf(mt1, __shfl_xor_sync(0xffffffffu, mt1, 2));
        const float mn0 = fmaxf(mr0, mt0);
        const float mn1 = fmaxf(mr1, mt1);
        const float al0 = __expf(mr0 - mn0);
        const float al1 = __expf(mr1 - mn1);
        float sum0 = 0.f, sum1 = 0.f;
#pragma unroll
        for (int nf = 0; nf < 8; nf++) {
            s[nf][0] = __expf(s[nf][0] - mn0);
            s[nf][1] = __expf(s[nf][1] - mn0);
            s[nf][2] = __expf(s[nf][2] - mn1);
            s[nf][3] = __expf(s[nf][3] - mn1);
            sum0 += s[nf][0] + s[nf][1];
            sum1 += s[nf][2] + s[nf][3];
        }
        sum0 += __shfl_xor_sync(0xffffffffu, sum0, 1);
        sum0 += __shfl_xor_sync(0xffffffffu, sum0, 2);
        sum1 += __shfl_xor_sync(0xffffffffu, sum1, 1);
        sum1 += __shfl_xor_sync(0xffffffffu, sum1, 2);
        lr0 = lr0 * al0 + sum0;
        lr1 = lr1 * al1 + sum1;
        mr0 = mn0; mr1 = mn1;
#pragma unroll
        for (int nf = 0; nf < 8; nf++) {
            o[nf][0] *= al0; o[nf][1] *= al0;
            o[nf][2] *= al1; o[nf][3] *= al1;
        }

#pragma unroll
        for (int nf = 0; nf < 8; nf++) {
            const int c0 = nf * 8 + 2 * t;
            float2 p0, p1;
            p0.x = to_tf32(s[nf][0]); p0.y = to_tf32(s[nf][1]);
            p1.x = to_tf32(s[nf][2]); p1.y = to_tf32(s[nf][3]);
            *(float2*)(sP + r0 * 68 + c0) = p0;
            *(float2*)(sP + r1 * 68 + c0) = p1;
        }
        __syncwarp();
        __syncthreads();

#pragma unroll
        for (int kb8 = 0; kb8 < 8; kb8++) {
            const int kb = kb8 * 8;
            uint32_t a[4];
            {
                const float* bp = sP + r0 * 68 + kb + t;
                a[0] = __float_as_uint(bp[0]);
                a[1] = __float_as_uint(bp[8 * 68]);
                a[2] = __float_as_uint(bp[4]);
                a[3] = __float_as_uint(bp[8 * 68 + 4]);
            }
#pragma unroll
            for (int nf = 0; nf < 8; nf++) {
                uint32_t bf[2];
                bf[0] = __float_as_uint(sV[(kb + t) * 72 + nf * 8 + g]);
                bf[1] = __float_as_uint(sV[(kb + t + 4) * 72 + nf * 8 + g]);
                mma_tf32(o[nf], a, bf);
            }
        }
    }

    const float inv0 = 1.f / lr0;
    const float inv1 = 1.f / lr1;
#pragma unroll
    for (int nf = 0; nf < 8; nf++) {
        const int c0 = nf * 8 + 2 * t;
        float2 v0, v1;
        v0.x = o[nf][0] * inv0; v0.y = o[nf][1] * inv0;
        v1.x = o[nf][2] * inv1; v1.y = o[nf][3] * inv1;
        *(float2*)&O[base + (qbase + r0) * EMB + c0] = v0;
        *(float2*)&O[base + (qbase + r1) * EMB + c0] = v1;
    }
}

// ---------------------------------------------------------------------------
extern "C" void kernel_launch(void* const* d_in, const int* in_sizes, int n_in,
                              void* d_out, int out_size)
{
    const float* xq = (const float*)d_in[0];
    const float* xk = (const float*)d_in[1];
    const float* xv = (const float*)d_in[2];
    // d_in[3] = attn_mask (causal triu) — implemented analytically, ignored
    const float* Wq = (const float*)d_in[4];
    const float* Wk = (const float*)d_in[5];
    const float* Wv = (const float*)d_in[6];
    const float* Wo = (const float*)d_in[7];
    const float* bo = (const float*)d_in[8];
    float* out = (float*)d_out;

    float *q, *k, *v, *c;
    cudaGetSymbolAddress((void**)&q, g_Q);
    cudaGetSymbolAddress((void**)&k, g_K);
    cudaGetSymbolAddress((void**)&v, g_V);
    cudaGetSymbolAddress((void**)&c, g_C);

    cudaFuncSetAttribute(attn_tc, cudaFuncAttributeMaxDynamicSharedMemorySize,
                         ATT_SMEM);
    cudaFuncSetAttribute(qkv_gemm, cudaFuncAttributeMaxDynamicSharedMemorySize,
                         GEMM_SMEM);
    cudaFuncSetAttribute(out_gemm, cudaFuncAttributeMaxDynamicSharedMemorySize,
                         GEMM_SMEM);

    dim3 gqkv(EMB / 128, (BSZ * NSEQ) / 128, 3);  // (8, 64, 3)
    qkv_gemm<<<gqkv, 256, GEMM_SMEM>>>(xq, xk, xv, Wq, Wk, Wv, q, k, v);

    attn_tc<<<dim3(NSEQ / 64, BSZ * HNUM), 128, ATT_SMEM>>>(q, k, v, c);

    out_gemm<<<dim3(EMB / 128, (BSZ * NSEQ) / 128), 256, GEMM_SMEM>>>(c, Wo, bo, out);
}